// round 16
// baseline (speedup 1.0000x reference)
#include <cuda_runtime.h>
#include <cstdint>
#include <cstddef>

#define NB 8
#define LL 2048
#define KK 30
#define CH 128
#define NEDGE (NB*LL*KK)   // 491520

static constexpr size_t V_SIZE = (size_t)NB * LL * CH;           // 2,097,152
static constexpr size_t E_SIZE = (size_t)NB * LL * KK * CH;      // 62,914,560
static constexpr size_t E_OFF  = V_SIZE;
static constexpr size_t I_OFF  = V_SIZE + E_SIZE;

// -------- scratch (device globals; no allocations allowed) --------
__device__ float g_dnb[NB*LL*KK];      // sorted neighbor distances
__device__ int   g_eidx[NB*LL*KK];     // sorted neighbor indices
__device__ float g_O[NB*LL*9];         // per-residue orientation frames
__device__ float g_feat[39*NEDGE];     // edge features, f-major
__device__ ulonglong2 g_W4[39*32];     // quad weights: ch 4l..4l+3 as 2 f32x2

// ---------------- small helpers ----------------
__device__ __forceinline__ float dot3(const float* a, const float* b) {
    return a[0]*b[0] + a[1]*b[1] + a[2]*b[2];
}
__device__ __forceinline__ void cross3(const float* a, const float* b, float* o) {
    o[0] = a[1]*b[2] - a[2]*b[1];
    o[1] = a[2]*b[0] - a[0]*b[2];
    o[2] = a[0]*b[1] - a[1]*b[0];
}
__device__ __forceinline__ void norm3(float* v) {
    float n = sqrtf(v[0]*v[0] + v[1]*v[1] + v[2]*v[2]);
    n = fmaxf(n, 1e-12f);
    v[0] /= n; v[1] /= n; v[2] /= n;
}
__device__ __forceinline__ float sgnf(float v) {
    return (v > 0.f) ? 1.f : ((v < 0.f) ? -1.f : 0.f);
}

// packed fp32x2 ops (sm_103a)
__device__ __forceinline__ unsigned long long pack2(float x, float y) {
    unsigned long long r;
    asm("mov.b64 %0, {%1, %2};" : "=l"(r) : "f"(x), "f"(y));
    return r;
}
__device__ __forceinline__ float2 unpack2(unsigned long long v) {
    float2 r;
    asm("mov.b64 {%0, %1}, %2;" : "=f"(r.x), "=f"(r.y) : "l"(v));
    return r;
}
__device__ __forceinline__ void fma2(unsigned long long& d,
                                     unsigned long long a, unsigned long long b) {
    asm("fma.rn.f32x2 %0, %1, %2, %0;" : "+l"(d) : "l"(a), "l"(b));
}
__device__ __forceinline__ unsigned long long add2(unsigned long long a,
                                                   unsigned long long b) {
    unsigned long long r;
    asm("add.rn.f32x2 %0, %1, %2;" : "=l"(r) : "l"(a), "l"(b));
    return r;
}

// cp.async 16B
__device__ __forceinline__ void cp16(void* sdst, const void* gsrc) {
    unsigned s = (unsigned)__cvta_generic_to_shared(sdst);
    asm volatile("cp.async.cg.shared.global [%0], [%1], 16;" :: "r"(s), "l"(gsrc));
}
#define CP_COMMIT() asm volatile("cp.async.commit_group;" ::: "memory")
#define CP_WAIT(n)  asm volatile("cp.async.wait_group %0;" :: "n"(n) : "memory")

// ======================================================================
// Kernel 1: exact KNN matching jax.lax.top_k(-D) bit-for-bit.
// Persistent-shaped grid: dim3(55, NB) ~= one full wave (148 SMs x 3
// blocks @ 33KB smem). Each warp loops over queries i += gridDim.x*16.
// Per-query body identical to the proven R14 version.
// ======================================================================
__global__ void __launch_bounds__(512)
knn_kernel(const float* __restrict__ X, float* __restrict__ out)
{
    __shared__ float4 pts[LL];                 // 32 KB
    const int b = blockIdx.y;
    const float* Xb = X + (size_t)b * LL * 12;

    for (int t = threadIdx.x; t < LL; t += blockDim.x) {
        pts[t] = make_float4(Xb[t*12 + 3], Xb[t*12 + 4], Xb[t*12 + 5], 0.f);
    }
    __syncthreads();

    const int wid  = threadIdx.x >> 5;
    const int lane = threadIdx.x & 31;
    const unsigned FULL = 0xffffffffu;
    const int qstride = gridDim.x * 16;

    for (int i = blockIdx.x * 16 + wid; i < LL; i += qstride) {
        const float4 q = pts[i];

        auto exact_key = [&](float px, float py, float pz, int j) -> unsigned long long {
            float dx = __fsub_rn(px, q.x);
            float dy = __fsub_rn(py, q.y);
            float dz = __fsub_rn(pz, q.z);
            float d2 = __fadd_rn(__fadd_rn(__fmul_rn(dx,dx), __fmul_rn(dy,dy)),
                                 __fmul_rn(dz,dz));
            float D  = sqrtf(__fadd_rn(d2, 1e-6f));   // sqrt.rn — matches XLA
            return ((unsigned long long)__float_as_uint(D) << 32) | (unsigned)j;
        };

        float4 p0 = pts[lane];
        unsigned long long cur = exact_key(p0.x, p0.y, p0.z, lane);

        unsigned long long thr;
        float thr_d2;
        auto update_key = [&]() {
            unsigned hi = __reduce_max_sync(FULL, (unsigned)(cur >> 32));
            unsigned lo = __reduce_max_sync(FULL,
                              ((unsigned)(cur >> 32) == hi) ? (unsigned)cur : 0u);
            thr = ((unsigned long long)hi << 32) | lo;
        };
        auto refresh_d2 = [&]() {
            float D = __uint_as_float((unsigned)(thr >> 32));
            thr_d2 = D * D * 1.00002f;     // conservative vs fma/rn/sqrt ulps
        };
        update_key(); refresh_d2();

        auto process = [&](unsigned bal, const float4& p, int jbase) {
            bool pass = (bal >> lane) & 1u;
            unsigned long long kk = pass ? exact_key(p.x, p.y, p.z, jbase + lane)
                                         : ~0ull;
            do {
                int s = __ffs(bal) - 1;
                bal &= bal - 1;
                unsigned long long bk = __shfl_sync(FULL, kk, s);
                if (bk < thr) {                       // warp-uniform
                    unsigned m = __ballot_sync(FULL, cur == thr);  // keys unique
                    if (lane == (__ffs(m) - 1)) cur = bk;
                    update_key();
                }
            } while (bal);
            refresh_d2();
        };

        // peel t = 1 (63 scan rounds total; pairs start at t=2)
        {
            float4 pa = pts[32 + lane];
            float dxa = pa.x - q.x, dya = pa.y - q.y, dza = pa.z - q.z;
            float d2a = fmaf(dxa, dxa, fmaf(dya, dya, dza*dza));
            unsigned bal_a = __ballot_sync(FULL, d2a <= thr_d2);
            if (bal_a) process(bal_a, pa, 32);
        }

        #pragma unroll 1
        for (int t = 2; t < LL/32; t += 2) {   // t = 2,4,...,62; pairs (t, t+1)
            const int j0 = t*32 + lane;
            float4 pa = pts[j0];
            float4 pb = pts[j0 + 32];
            float dxa = pa.x - q.x, dya = pa.y - q.y, dza = pa.z - q.z;
            float dxb = pb.x - q.x, dyb = pb.y - q.y, dzb = pb.z - q.z;
            float d2a = fmaf(dxa, dxa, fmaf(dya, dya, dza*dza));
            float d2b = fmaf(dxb, dxb, fmaf(dyb, dyb, dzb*dzb));
            unsigned bal_a = __ballot_sync(FULL, d2a <= thr_d2);
            unsigned bal_b = __ballot_sync(FULL, d2b <= thr_d2);
            if (bal_a) process(bal_a, pa, t*32);
            if (bal_b) process(bal_b, pb, t*32 + 32);
        }

        // bitonic sort 32 keys across the warp, ascending
        unsigned long long sk = cur;
        #pragma unroll
        for (int k = 2; k <= 32; k <<= 1) {
            #pragma unroll
            for (int j = k >> 1; j >= 1; j >>= 1) {
                unsigned long long ok = __shfl_xor_sync(FULL, sk, j);
                bool up    = ((lane & k) == 0);
                bool lower = ((lane & j) == 0);
                bool mineLess = (sk < ok);
                bool takeOther = up ? (lower ? !mineLess : mineLess)
                                    : (lower ? mineLess : !mineLess);
                if (takeOther) sk = ok;
            }
        }

        if (lane < KK) {
            int e = (b*LL + i)*KK + lane;
            int nidx = (int)(sk & 0xffffffffu);
            g_dnb[e]  = __uint_as_float((unsigned)(sk >> 32));
            g_eidx[e] = nidx;
            out[I_OFF + (size_t)e] = (float)nidx;
        }
    }
}

// ======================================================================
// Kernel 2: node features (dihedrals -> 6) @ W_node + LN; also builds O.
// Warp-per-residue: 8 residues per 256-thread block; lane owns 4 channels.
// ======================================================================
__global__ void __launch_bounds__(256)
node_kernel(const float* __restrict__ X,
            const float* __restrict__ Wn, const float* __restrict__ bn,
            const float* __restrict__ gn, const float* __restrict__ betan,
            float* __restrict__ out)
{
    const int w    = threadIdx.x >> 5;
    const int lane = threadIdx.x & 31;
    const int idx  = blockIdx.x * 8 + w;    // b*LL + i
    const int b = idx / LL, i = idx % LL;
    const float* Xb = X + (size_t)b * LL * 12;

    __shared__ float feat[8][8];

    if (lane < 3) {
        int t = 3*i + lane - 1;
        float ang = 0.f;
        if (t >= 0 && t <= 3*LL - 4) {
            float P[4][3];
            #pragma unroll
            for (int a = 0; a < 4; a++) {
                int g = t + a;
                const float* ptr = Xb + (g/3)*12 + (g%3)*3;
                P[a][0] = ptr[0]; P[a][1] = ptr[1]; P[a][2] = ptr[2];
            }
            float u2[3], u1[3], u0[3], n2[3], n1[3];
            #pragma unroll
            for (int c = 0; c < 3; c++) {
                u2[c] = P[1][c] - P[0][c];
                u1[c] = P[2][c] - P[1][c];
                u0[c] = P[3][c] - P[2][c];
            }
            norm3(u2); norm3(u1); norm3(u0);
            cross3(u2, u1, n2); norm3(n2);
            cross3(u1, u0, n1); norm3(n1);
            float cd = dot3(n2, n1);
            cd = fminf(fmaxf(cd, -1.f + 1e-7f), 1.f - 1e-7f);
            ang = sgnf(dot3(u2, n1)) * acosf(cd);
        }
        feat[w][lane]     = cosf(ang);
        feat[w][lane + 3] = sinf(ang);
    }
    if (lane == 3) {
        const float* pr = Xb + i*12;
        float N[3]  = {pr[0], pr[1], pr[2]};
        float CA[3] = {pr[3], pr[4], pr[5]};
        float C[3]  = {pr[6], pr[7], pr[8]};
        float nca[3], cac[3];
        #pragma unroll
        for (int c = 0; c < 3; c++) { nca[c] = CA[c] - N[c]; cac[c] = C[c] - CA[c]; }
        norm3(nca); norm3(cac);
        float n1[3]; cross3(nca, cac, n1); norm3(n1);
        float bb[3];
        #pragma unroll
        for (int c = 0; c < 3; c++) bb[c] = cac[c] - nca[c];
        norm3(bb);
        float xx[3]; cross3(bb, n1, xx); norm3(xx);
        float* o = g_O + (size_t)idx * 9;
        o[0]=bb[0]; o[1]=bb[1]; o[2]=bb[2];
        o[3]=n1[0]; o[4]=n1[1]; o[5]=n1[2];
        o[6]=xx[0]; o[7]=xx[1]; o[8]=xx[2];
    }
    __syncwarp();

    float f[6];
    #pragma unroll
    for (int k = 0; k < 6; k++) f[k] = feat[w][k];

    float4 acc = reinterpret_cast<const float4*>(bn)[lane];
    #pragma unroll
    for (int k = 0; k < 6; k++) {
        float4 w4 = reinterpret_cast<const float4*>(Wn + k*CH)[lane];
        acc.x += f[k] * w4.x;
        acc.y += f[k] * w4.y;
        acc.z += f[k] * w4.z;
        acc.w += f[k] * w4.w;
    }

    float s1 = (acc.x + acc.y) + (acc.z + acc.w);
    float s2 = acc.x*acc.x + acc.y*acc.y + acc.z*acc.z + acc.w*acc.w;
    #pragma unroll
    for (int o = 16; o > 0; o >>= 1) {
        s1 += __shfl_xor_sync(0xffffffffu, s1, o);
        s2 += __shfl_xor_sync(0xffffffffu, s2, o);
    }
    float mu  = s1 * (1.f/128.f);
    float var = s2 * (1.f/128.f) - mu*mu;
    float ir  = 1.f / sqrtf(var + 1e-5f);

    float4 g4 = reinterpret_cast<const float4*>(gn)[lane];
    float4 t4 = reinterpret_cast<const float4*>(betan)[lane];
    float4 o4;
    o4.x = (acc.x - mu) * ir * g4.x + t4.x;
    o4.y = (acc.y - mu) * ir * g4.y + t4.y;
    o4.z = (acc.z - mu) * ir * g4.z + t4.z;
    o4.w = (acc.w - mu) * ir * g4.w + t4.w;
    reinterpret_cast<float4*>(out + (size_t)idx * CH)[lane] = o4;
}

// ======================================================================
// Kernel 3: edge features (39 per edge), one thread per edge, f-major out.
// Block 0 additionally packs the quad weights (contiguous channels) into g_W4.
// ======================================================================
__global__ void __launch_bounds__(256)
efeat_kernel(const float* __restrict__ X, const float* __restrict__ We)
{
    if (blockIdx.x == 0) {
        for (int idx = threadIdx.x; idx < 39*32; idx += 256) {
            int f = idx >> 5, l = idx & 31;
            g_W4[idx] = make_ulonglong2(
                pack2(We[f*CH + 4*l],     We[f*CH + 4*l + 1]),
                pack2(We[f*CH + 4*l + 2], We[f*CH + 4*l + 3]));
        }
    }

    const int e = blockIdx.x * 256 + threadIdx.x;
    if (e >= NEDGE) return;
    const int bi = e / KK;                 // b*LL + i
    const int b = bi / LL, i = bi % LL;
    const int j = g_eidx[e];
    const float D = g_dnb[e];

    float F[39];

    const float d = (float)(j - i);
    const float FR[8] = {1.0f, 0.31622776601683794f, 0.1f,
                         0.031622776601683791f, 0.01f,
                         0.0031622776601683794f, 0.001f,
                         0.00031622776601683794f};   // 10^(-m/2)
    #pragma unroll
    for (int m = 0; m < 8; m++) {
        float a = d * FR[m];
        float sv, cv;
        sincosf(a, &sv, &cv);
        F[m]     = cv;
        F[8 + m] = sv;
    }

    #pragma unroll
    for (int m = 0; m < 16; m++) {
        float mu = (float)m * (20.0f / 15.0f);
        float t = (D - mu) / 1.25f;
        F[16 + m] = expf(-(t * t));
    }

    const float* Oi = g_O + (size_t)bi * 9;
    const float* Oj = g_O + ((size_t)b*LL + j) * 9;
    float oi[9], oj[9];
    #pragma unroll
    for (int t = 0; t < 9; t++) { oi[t] = Oi[t]; oj[t] = Oj[t]; }
    const float* Xi = X + (size_t)bi * 12 + 3;
    const float* Xj = X + ((size_t)b*LL + j) * 12 + 3;
    float dX[3] = {Xj[0]-Xi[0], Xj[1]-Xi[1], Xj[2]-Xi[2]};
    float du[3] = { oi[0]*dX[0] + oi[1]*dX[1] + oi[2]*dX[2],
                    oi[3]*dX[0] + oi[4]*dX[1] + oi[5]*dX[2],
                    oi[6]*dX[0] + oi[7]*dX[1] + oi[8]*dX[2] };
    norm3(du);
    F[32] = du[0]; F[33] = du[1]; F[34] = du[2];

    float R[3][3];
    #pragma unroll
    for (int r = 0; r < 3; r++)
        #pragma unroll
        for (int c = 0; c < 3; c++)
            R[r][c] = oi[r]*oj[c] + oi[3+r]*oj[3+c] + oi[6+r]*oj[6+c];

    float Rxx = R[0][0], Ryy = R[1][1], Rzz = R[2][2];
    float m0 = 0.5f * sqrtf(fabsf((1.f + ( Rxx - Ryy - Rzz)) + 1e-10f));
    float m1 = 0.5f * sqrtf(fabsf((1.f + (-Rxx + Ryy - Rzz)) + 1e-10f));
    float m2 = 0.5f * sqrtf(fabsf((1.f + (-Rxx - Ryy + Rzz)) + 1e-10f));
    float qx = sgnf(R[2][1] - R[1][2]) * m0;
    float qy = sgnf(R[0][2] - R[2][0]) * m1;
    float qz = sgnf(R[1][0] - R[0][1]) * m2;
    float qw = sqrtf(fmaxf(1.f + Rxx + Ryy + Rzz, 0.f)) * 0.5f;
    float qn = sqrtf(qx*qx + qy*qy + qz*qz + qw*qw);
    qn = fmaxf(qn, 1e-12f);
    F[35] = qx/qn; F[36] = qy/qn; F[37] = qz/qn; F[38] = qw/qn;

    #pragma unroll
    for (int f = 0; f < 39; f++) g_feat[(size_t)f * NEDGE + e] = F[f];
}

// ======================================================================
// Kernel 4: edge GEMM + bias + LN, cp.async double-buffered over NT tiles.
// (R14 structure — best measured.)
// ======================================================================
#define TILE 128
#define NT 4
#define NCHUNK (39*TILE/4)   // 1248 16B-chunks per tile

__global__ void __launch_bounds__(256, 2)
egemm_kernel(const float* __restrict__ be,
             const float* __restrict__ ge, const float* __restrict__ betae,
             float* __restrict__ out)
{
    const int t = threadIdx.x;
    const int h = t >> 5;             // warp id: edges [h*16, h*16+16)
    const int l = t & 31;             // lane: channels 4l..4l+3

    __shared__ __align__(16) ulonglong2 W4s[39*32];      // 19,968 B
    __shared__ __align__(16) float ftile[2][39*TILE];    // 2 x 19,968 B

    // weights once per block
    {
        const ulonglong2* src = reinterpret_cast<const ulonglong2*>(g_W4);
        #pragma unroll
        for (int k = 0; k < 5; k++) {
            int idx = t + k*256;
            if (idx < 39*32) W4s[idx] = src[idx];
        }
    }

    const int tile0 = blockIdx.x * NT;

    auto issue_tile = [&](int tile, int buf) {
        const int e0 = tile * TILE;
        #pragma unroll
        for (int k = 0; k < 5; k++) {
            int idx = t + k*256;
            if (idx < NCHUNK) {
                int f = idx >> 5, e4 = idx & 31;       // 32 chunks per f-row
                cp16(&ftile[buf][f*TILE + e4*4],
                     &g_feat[(size_t)f * NEDGE + e0 + e4*4]);
            }
        }
    };

    // prefetch tile 0
    issue_tile(tile0, 0);
    CP_COMMIT();

    const float4 b4 = reinterpret_cast<const float4*>(be)[l];
    const float4 g4 = reinterpret_cast<const float4*>(ge)[l];
    const float4 t4 = reinterpret_cast<const float4*>(betae)[l];

    #pragma unroll 1
    for (int it = 0; it < NT; it++) {
        if (it + 1 < NT) {
            issue_tile(tile0 + it + 1, (it + 1) & 1);
            CP_COMMIT();
            CP_WAIT(1);
        } else {
            CP_WAIT(0);
        }
        __syncthreads();

        const float* buf = ftile[it & 1];
        const int e0 = (tile0 + it) * TILE;

        // acc[p][c]: edge pair (h*16+2p, h*16+2p+1), channel 4l+c
        unsigned long long acc[8][4];
        {
            unsigned long long b0 = pack2(b4.x, b4.x);
            unsigned long long b1 = pack2(b4.y, b4.y);
            unsigned long long b2 = pack2(b4.z, b4.z);
            unsigned long long b3 = pack2(b4.w, b4.w);
            #pragma unroll
            for (int p = 0; p < 8; p++) {
                acc[p][0] = b0; acc[p][1] = b1; acc[p][2] = b2; acc[p][3] = b3;
            }
        }

        #pragma unroll
        for (int f = 0; f < 39; f++) {
            ulonglong2 wq = W4s[f*32 + l];               // (w0,w1),(w2,w3)
            float2 wx = unpack2(wq.x);
            float2 wy = unpack2(wq.y);
            unsigned long long wd0 = pack2(wx.x, wx.x);
            unsigned long long wd1 = pack2(wx.y, wx.y);
            unsigned long long wd2 = pack2(wy.x, wy.x);
            unsigned long long wd3 = pack2(wy.y, wy.y);
            const ulonglong2* fp = reinterpret_cast<const ulonglong2*>(
                buf + f*TILE + h*16);                    // broadcast LDS.128
            #pragma unroll
            for (int k = 0; k < 4; k++) {
                ulonglong2 v = fp[k];   // v.x=(f_e,f_e+1), v.y=(f_e+2,f_e+3)
                fma2(acc[2*k  ][0], wd0, v.x);
                fma2(acc[2*k  ][1], wd1, v.x);
                fma2(acc[2*k  ][2], wd2, v.x);
                fma2(acc[2*k  ][3], wd3, v.x);
                fma2(acc[2*k+1][0], wd0, v.y);
                fma2(acc[2*k+1][1], wd1, v.y);
                fma2(acc[2*k+1][2], wd2, v.y);
                fma2(acc[2*k+1][3], wd3, v.y);
            }
        }

        // epilogue: LN per edge; (s1,s2) packed as one f32x2 chain per parity
        #pragma unroll
        for (int p = 0; p < 8; p++) {
            float2 a0 = unpack2(acc[p][0]);
            float2 a1 = unpack2(acc[p][1]);
            float2 a2 = unpack2(acc[p][2]);
            float2 a3 = unpack2(acc[p][3]);
            float s1e = (a0.x + a1.x) + (a2.x + a3.x);
            float s1o = (a0.y + a1.y) + (a2.y + a3.y);
            float s2e = a0.x*a0.x + a1.x*a1.x + a2.x*a2.x + a3.x*a3.x;
            float s2o = a0.y*a0.y + a1.y*a1.y + a2.y*a2.y + a3.y*a3.y;
            unsigned long long se = pack2(s1e, s2e);
            unsigned long long so = pack2(s1o, s2o);
            #pragma unroll
            for (int o = 16; o > 0; o >>= 1) {
                se = add2(se, __shfl_xor_sync(0xffffffffu, se, o));
                so = add2(so, __shfl_xor_sync(0xffffffffu, so, o));
            }
            float2 re = unpack2(se);   // (s1e, s2e)
            float2 ro = unpack2(so);   // (s1o, s2o)
            float mue  = re.x * (1.f/128.f);
            float muo  = ro.x * (1.f/128.f);
            float ire  = 1.f / sqrtf(re.y * (1.f/128.f) - mue*mue + 1e-5f);
            float iro  = 1.f / sqrtf(ro.y * (1.f/128.f) - muo*muo + 1e-5f);

            int ee = e0 + h*16 + 2*p;
            float4 oe, oo;
            oe.x = (a0.x - mue) * ire * g4.x + t4.x;
            oe.y = (a1.x - mue) * ire * g4.y + t4.y;
            oe.z = (a2.x - mue) * ire * g4.z + t4.z;
            oe.w = (a3.x - mue) * ire * g4.w + t4.w;
            oo.x = (a0.y - muo) * iro * g4.x + t4.x;
            oo.y = (a1.y - muo) * iro * g4.y + t4.y;
            oo.z = (a2.y - muo) * iro * g4.z + t4.z;
            oo.w = (a3.y - muo) * iro * g4.w + t4.w;
            reinterpret_cast<float4*>(out + E_OFF + (size_t)ee * CH)[l]       = oe;
            reinterpret_cast<float4*>(out + E_OFF + (size_t)(ee + 1) * CH)[l] = oo;
        }
        __syncthreads();   // buffer free before it+2 overwrite
    }
}

// ======================================================================
extern "C" void kernel_launch(void* const* d_in, const int* in_sizes, int n_in,
                              void* d_out, int out_size)
{
    const float* X      = (const float*)d_in[0];
    // d_in[1] = mask (all ones; unused)
    const float* W_node = (const float*)d_in[2];
    const float* b_node = (const float*)d_in[3];
    const float* g_node = (const float*)d_in[4];
    const float* be_node= (const float*)d_in[5];
    const float* W_edge = (const float*)d_in[6];
    const float* b_edge = (const float*)d_in[7];
    const float* g_edge = (const float*)d_in[8];
    const float* be_edge= (const float*)d_in[9];
    float* out = (float*)d_out;

    knn_kernel<<<dim3(55, NB), 512>>>(X, out);
    node_kernel<<<NB*LL/8, 256>>>(X, W_node, b_node, g_node, be_node, out);
    efeat_kernel<<<(NEDGE + 255)/256, 256>>>(X, W_edge);
    egemm_kernel<<<NEDGE/(TILE*NT), 256>>>(b_edge, g_edge, be_edge, out);
}

// round 17
// speedup vs baseline: 1.1813x; 1.1813x over previous
#include <cuda_runtime.h>
#include <cstdint>
#include <cstddef>

#define NB 8
#define LL 2048
#define KK 30
#define CH 128
#define NEDGE (NB*LL*KK)   // 491520

static constexpr size_t V_SIZE = (size_t)NB * LL * CH;           // 2,097,152
static constexpr size_t E_SIZE = (size_t)NB * LL * KK * CH;      // 62,914,560
static constexpr size_t E_OFF  = V_SIZE;
static constexpr size_t I_OFF  = V_SIZE + E_SIZE;

// -------- scratch (device globals; no allocations allowed) --------
__device__ float g_dnb[NB*LL*KK];      // sorted neighbor distances
__device__ int   g_eidx[NB*LL*KK];     // sorted neighbor indices
__device__ float g_O[NB*LL*9];         // per-residue orientation frames
__device__ float g_feat[39*NEDGE];     // edge features, f-major
__device__ ulonglong2 g_W4[39*32];     // quad weights: ch 4l..4l+3 as 2 f32x2

// ---------------- small helpers ----------------
__device__ __forceinline__ float dot3(const float* a, const float* b) {
    return a[0]*b[0] + a[1]*b[1] + a[2]*b[2];
}
__device__ __forceinline__ void cross3(const float* a, const float* b, float* o) {
    o[0] = a[1]*b[2] - a[2]*b[1];
    o[1] = a[2]*b[0] - a[0]*b[2];
    o[2] = a[0]*b[1] - a[1]*b[0];
}
__device__ __forceinline__ void norm3(float* v) {
    float n = sqrtf(v[0]*v[0] + v[1]*v[1] + v[2]*v[2]);
    n = fmaxf(n, 1e-12f);
    v[0] /= n; v[1] /= n; v[2] /= n;
}
__device__ __forceinline__ float sgnf(float v) {
    return (v > 0.f) ? 1.f : ((v < 0.f) ? -1.f : 0.f);
}

// packed fp32x2 ops (sm_103a)
__device__ __forceinline__ unsigned long long pack2(float x, float y) {
    unsigned long long r;
    asm("mov.b64 %0, {%1, %2};" : "=l"(r) : "f"(x), "f"(y));
    return r;
}
__device__ __forceinline__ float2 unpack2(unsigned long long v) {
    float2 r;
    asm("mov.b64 {%0, %1}, %2;" : "=f"(r.x), "=f"(r.y) : "l"(v));
    return r;
}
__device__ __forceinline__ void fma2(unsigned long long& d,
                                     unsigned long long a, unsigned long long b) {
    asm("fma.rn.f32x2 %0, %1, %2, %0;" : "+l"(d) : "l"(a), "l"(b));
}
__device__ __forceinline__ unsigned long long add2(unsigned long long a,
                                                   unsigned long long b) {
    unsigned long long r;
    asm("add.rn.f32x2 %0, %1, %2;" : "=l"(r) : "l"(a), "l"(b));
    return r;
}

// cp.async 16B
__device__ __forceinline__ void cp16(void* sdst, const void* gsrc) {
    unsigned s = (unsigned)__cvta_generic_to_shared(sdst);
    asm volatile("cp.async.cg.shared.global [%0], [%1], 16;" :: "r"(s), "l"(gsrc));
}
#define CP_COMMIT() asm volatile("cp.async.commit_group;" ::: "memory")
#define CP_WAIT(n)  asm volatile("cp.async.wait_group %0;" :: "n"(n) : "memory")

// ======================================================================
// Kernel 1: exact KNN matching jax.lax.top_k(-D) bit-for-bit.
// (R14 config — proven 114us; grid dim3(LL/16, NB).)
// ======================================================================
__global__ void __launch_bounds__(512)
knn_kernel(const float* __restrict__ X, float* __restrict__ out)
{
    __shared__ float4 pts[LL];                 // 32 KB
    const int b = blockIdx.y;
    const float* Xb = X + (size_t)b * LL * 12;

    for (int t = threadIdx.x; t < LL; t += blockDim.x) {
        pts[t] = make_float4(Xb[t*12 + 3], Xb[t*12 + 4], Xb[t*12 + 5], 0.f);
    }
    __syncthreads();

    const int wid  = threadIdx.x >> 5;
    const int lane = threadIdx.x & 31;
    const int i = blockIdx.x * 16 + wid;       // query index
    const float4 q = pts[i];
    const unsigned FULL = 0xffffffffu;

    auto exact_key = [&](float px, float py, float pz, int j) -> unsigned long long {
        float dx = __fsub_rn(px, q.x);
        float dy = __fsub_rn(py, q.y);
        float dz = __fsub_rn(pz, q.z);
        float d2 = __fadd_rn(__fadd_rn(__fmul_rn(dx,dx), __fmul_rn(dy,dy)),
                             __fmul_rn(dz,dz));
        float D  = sqrtf(__fadd_rn(d2, 1e-6f));   // sqrt.rn — matches XLA
        return ((unsigned long long)__float_as_uint(D) << 32) | (unsigned)j;
    };

    float4 p0 = pts[lane];
    unsigned long long cur = exact_key(p0.x, p0.y, p0.z, lane);

    unsigned long long thr;
    float thr_d2;
    auto update_key = [&]() {
        unsigned hi = __reduce_max_sync(FULL, (unsigned)(cur >> 32));
        unsigned lo = __reduce_max_sync(FULL,
                          ((unsigned)(cur >> 32) == hi) ? (unsigned)cur : 0u);
        thr = ((unsigned long long)hi << 32) | lo;
    };
    auto refresh_d2 = [&]() {
        float D = __uint_as_float((unsigned)(thr >> 32));
        thr_d2 = D * D * 1.00002f;     // conservative vs fma/rn/sqrt ulps
    };
    update_key(); refresh_d2();

    auto process = [&](unsigned bal, const float4& p, int jbase) {
        bool pass = (bal >> lane) & 1u;
        unsigned long long kk = pass ? exact_key(p.x, p.y, p.z, jbase + lane)
                                     : ~0ull;
        do {
            int s = __ffs(bal) - 1;
            bal &= bal - 1;
            unsigned long long bk = __shfl_sync(FULL, kk, s);
            if (bk < thr) {                       // warp-uniform
                unsigned m = __ballot_sync(FULL, cur == thr);  // keys unique
                if (lane == (__ffs(m) - 1)) cur = bk;
                update_key();
            }
        } while (bal);
        refresh_d2();
    };

    // peel t = 1 (63 scan rounds total; pairs start at t=2)
    {
        float4 pa = pts[32 + lane];
        float dxa = pa.x - q.x, dya = pa.y - q.y, dza = pa.z - q.z;
        float d2a = fmaf(dxa, dxa, fmaf(dya, dya, dza*dza));
        unsigned bal_a = __ballot_sync(FULL, d2a <= thr_d2);
        if (bal_a) process(bal_a, pa, 32);
    }

    #pragma unroll 1
    for (int t = 2; t < LL/32; t += 2) {       // t = 2,4,...,62; pairs (t, t+1)
        const int j0 = t*32 + lane;
        float4 pa = pts[j0];
        float4 pb = pts[j0 + 32];
        float dxa = pa.x - q.x, dya = pa.y - q.y, dza = pa.z - q.z;
        float dxb = pb.x - q.x, dyb = pb.y - q.y, dzb = pb.z - q.z;
        float d2a = fmaf(dxa, dxa, fmaf(dya, dya, dza*dza));
        float d2b = fmaf(dxb, dxb, fmaf(dyb, dyb, dzb*dzb));
        unsigned bal_a = __ballot_sync(FULL, d2a <= thr_d2);
        unsigned bal_b = __ballot_sync(FULL, d2b <= thr_d2);
        if (bal_a) process(bal_a, pa, t*32);
        if (bal_b) process(bal_b, pb, t*32 + 32);
    }

    // bitonic sort 32 keys across the warp, ascending
    #pragma unroll
    for (int k = 2; k <= 32; k <<= 1) {
        #pragma unroll
        for (int j = k >> 1; j >= 1; j >>= 1) {
            unsigned long long ok = __shfl_xor_sync(FULL, cur, j);
            bool up    = ((lane & k) == 0);
            bool lower = ((lane & j) == 0);
            bool mineLess = (cur < ok);
            bool takeOther = up ? (lower ? !mineLess : mineLess)
                                : (lower ? mineLess : !mineLess);
            if (takeOther) cur = ok;
        }
    }

    if (lane < KK) {
        int e = (b*LL + i)*KK + lane;
        int nidx = (int)(cur & 0xffffffffu);
        g_dnb[e]  = __uint_as_float((unsigned)(cur >> 32));
        g_eidx[e] = nidx;
        out[I_OFF + (size_t)e] = (float)nidx;
    }
}

// ======================================================================
// Kernel 2: node features (dihedrals -> 6) @ W_node + LN; also builds O.
// Warp-per-residue: 8 residues per 256-thread block; lane owns 4 channels.
// ======================================================================
__global__ void __launch_bounds__(256)
node_kernel(const float* __restrict__ X,
            const float* __restrict__ Wn, const float* __restrict__ bn,
            const float* __restrict__ gn, const float* __restrict__ betan,
            float* __restrict__ out)
{
    const int w    = threadIdx.x >> 5;
    const int lane = threadIdx.x & 31;
    const int idx  = blockIdx.x * 8 + w;    // b*LL + i
    const int b = idx / LL, i = idx % LL;
    const float* Xb = X + (size_t)b * LL * 12;

    __shared__ float feat[8][8];

    if (lane < 3) {
        int t = 3*i + lane - 1;
        float ang = 0.f;
        if (t >= 0 && t <= 3*LL - 4) {
            float P[4][3];
            #pragma unroll
            for (int a = 0; a < 4; a++) {
                int g = t + a;
                const float* ptr = Xb + (g/3)*12 + (g%3)*3;
                P[a][0] = ptr[0]; P[a][1] = ptr[1]; P[a][2] = ptr[2];
            }
            float u2[3], u1[3], u0[3], n2[3], n1[3];
            #pragma unroll
            for (int c = 0; c < 3; c++) {
                u2[c] = P[1][c] - P[0][c];
                u1[c] = P[2][c] - P[1][c];
                u0[c] = P[3][c] - P[2][c];
            }
            norm3(u2); norm3(u1); norm3(u0);
            cross3(u2, u1, n2); norm3(n2);
            cross3(u1, u0, n1); norm3(n1);
            float cd = dot3(n2, n1);
            cd = fminf(fmaxf(cd, -1.f + 1e-7f), 1.f - 1e-7f);
            ang = sgnf(dot3(u2, n1)) * acosf(cd);
        }
        feat[w][lane]     = cosf(ang);
        feat[w][lane + 3] = sinf(ang);
    }
    if (lane == 3) {
        const float* pr = Xb + i*12;
        float N[3]  = {pr[0], pr[1], pr[2]};
        float CA[3] = {pr[3], pr[4], pr[5]};
        float C[3]  = {pr[6], pr[7], pr[8]};
        float nca[3], cac[3];
        #pragma unroll
        for (int c = 0; c < 3; c++) { nca[c] = CA[c] - N[c]; cac[c] = C[c] - CA[c]; }
        norm3(nca); norm3(cac);
        float n1[3]; cross3(nca, cac, n1); norm3(n1);
        float bb[3];
        #pragma unroll
        for (int c = 0; c < 3; c++) bb[c] = cac[c] - nca[c];
        norm3(bb);
        float xx[3]; cross3(bb, n1, xx); norm3(xx);
        float* o = g_O + (size_t)idx * 9;
        o[0]=bb[0]; o[1]=bb[1]; o[2]=bb[2];
        o[3]=n1[0]; o[4]=n1[1]; o[5]=n1[2];
        o[6]=xx[0]; o[7]=xx[1]; o[8]=xx[2];
    }
    __syncwarp();

    float f[6];
    #pragma unroll
    for (int k = 0; k < 6; k++) f[k] = feat[w][k];

    float4 acc = reinterpret_cast<const float4*>(bn)[lane];
    #pragma unroll
    for (int k = 0; k < 6; k++) {
        float4 w4 = reinterpret_cast<const float4*>(Wn + k*CH)[lane];
        acc.x += f[k] * w4.x;
        acc.y += f[k] * w4.y;
        acc.z += f[k] * w4.z;
        acc.w += f[k] * w4.w;
    }

    float s1 = (acc.x + acc.y) + (acc.z + acc.w);
    float s2 = acc.x*acc.x + acc.y*acc.y + acc.z*acc.z + acc.w*acc.w;
    #pragma unroll
    for (int o = 16; o > 0; o >>= 1) {
        s1 += __shfl_xor_sync(0xffffffffu, s1, o);
        s2 += __shfl_xor_sync(0xffffffffu, s2, o);
    }
    float mu  = s1 * (1.f/128.f);
    float var = s2 * (1.f/128.f) - mu*mu;
    float ir  = 1.f / sqrtf(var + 1e-5f);

    float4 g4 = reinterpret_cast<const float4*>(gn)[lane];
    float4 t4 = reinterpret_cast<const float4*>(betan)[lane];
    float4 o4;
    o4.x = (acc.x - mu) * ir * g4.x + t4.x;
    o4.y = (acc.y - mu) * ir * g4.y + t4.y;
    o4.z = (acc.z - mu) * ir * g4.z + t4.z;
    o4.w = (acc.w - mu) * ir * g4.w + t4.w;
    reinterpret_cast<float4*>(out + (size_t)idx * CH)[lane] = o4;
}

// ======================================================================
// Kernel 3: edge features (39 per edge), one thread per edge, f-major out.
// Block 0 additionally packs the quad weights (contiguous channels) into g_W4.
// RBF uses __expf (MUFU path; ~1e-7 absolute feature error, negligible).
// ======================================================================
__global__ void __launch_bounds__(256)
efeat_kernel(const float* __restrict__ X, const float* __restrict__ We)
{
    if (blockIdx.x == 0) {
        for (int idx = threadIdx.x; idx < 39*32; idx += 256) {
            int f = idx >> 5, l = idx & 31;
            g_W4[idx] = make_ulonglong2(
                pack2(We[f*CH + 4*l],     We[f*CH + 4*l + 1]),
                pack2(We[f*CH + 4*l + 2], We[f*CH + 4*l + 3]));
        }
    }

    const int e = blockIdx.x * 256 + threadIdx.x;
    if (e >= NEDGE) return;
    const int bi = e / KK;                 // b*LL + i
    const int b = bi / LL, i = bi % LL;
    const int j = g_eidx[e];
    const float D = g_dnb[e];

    float F[39];

    const float d = (float)(j - i);
    const float FR[8] = {1.0f, 0.31622776601683794f, 0.1f,
                         0.031622776601683791f, 0.01f,
                         0.0031622776601683794f, 0.001f,
                         0.00031622776601683794f};   // 10^(-m/2)
    #pragma unroll
    for (int m = 0; m < 8; m++) {
        float a = d * FR[m];
        float sv, cv;
        sincosf(a, &sv, &cv);
        F[m]     = cv;
        F[8 + m] = sv;
    }

    #pragma unroll
    for (int m = 0; m < 16; m++) {
        float mu = (float)m * (20.0f / 15.0f);
        float t = (D - mu) / 1.25f;
        F[16 + m] = __expf(-(t * t));
    }

    const float* Oi = g_O + (size_t)bi * 9;
    const float* Oj = g_O + ((size_t)b*LL + j) * 9;
    float oi[9], oj[9];
    #pragma unroll
    for (int t = 0; t < 9; t++) { oi[t] = Oi[t]; oj[t] = Oj[t]; }
    const float* Xi = X + (size_t)bi * 12 + 3;
    const float* Xj = X + ((size_t)b*LL + j) * 12 + 3;
    float dX[3] = {Xj[0]-Xi[0], Xj[1]-Xi[1], Xj[2]-Xi[2]};
    float du[3] = { oi[0]*dX[0] + oi[1]*dX[1] + oi[2]*dX[2],
                    oi[3]*dX[0] + oi[4]*dX[1] + oi[5]*dX[2],
                    oi[6]*dX[0] + oi[7]*dX[1] + oi[8]*dX[2] };
    norm3(du);
    F[32] = du[0]; F[33] = du[1]; F[34] = du[2];

    float R[3][3];
    #pragma unroll
    for (int r = 0; r < 3; r++)
        #pragma unroll
        for (int c = 0; c < 3; c++)
            R[r][c] = oi[r]*oj[c] + oi[3+r]*oj[3+c] + oi[6+r]*oj[6+c];

    float Rxx = R[0][0], Ryy = R[1][1], Rzz = R[2][2];
    float m0 = 0.5f * sqrtf(fabsf((1.f + ( Rxx - Ryy - Rzz)) + 1e-10f));
    float m1 = 0.5f * sqrtf(fabsf((1.f + (-Rxx + Ryy - Rzz)) + 1e-10f));
    float m2 = 0.5f * sqrtf(fabsf((1.f + (-Rxx - Ryy + Rzz)) + 1e-10f));
    float qx = sgnf(R[2][1] - R[1][2]) * m0;
    float qy = sgnf(R[0][2] - R[2][0]) * m1;
    float qz = sgnf(R[1][0] - R[0][1]) * m2;
    float qw = sqrtf(fmaxf(1.f + Rxx + Ryy + Rzz, 0.f)) * 0.5f;
    float qn = sqrtf(qx*qx + qy*qy + qz*qz + qw*qw);
    qn = fmaxf(qn, 1e-12f);
    F[35] = qx/qn; F[36] = qy/qn; F[37] = qz/qn; F[38] = qw/qn;

    #pragma unroll
    for (int f = 0; f < 39; f++) g_feat[(size_t)f * NEDGE + e] = F[f];
}

// ======================================================================
// Kernel 4: edge GEMM + bias + LN, cp.async double-buffered over NT tiles.
// (R14 structure — best measured.)
// ======================================================================
#define TILE 128
#define NT 4
#define NCHUNK (39*TILE/4)   // 1248 16B-chunks per tile

__global__ void __launch_bounds__(256, 2)
egemm_kernel(const float* __restrict__ be,
             const float* __restrict__ ge, const float* __restrict__ betae,
             float* __restrict__ out)
{
    const int t = threadIdx.x;
    const int h = t >> 5;             // warp id: edges [h*16, h*16+16)
    const int l = t & 31;             // lane: channels 4l..4l+3

    __shared__ __align__(16) ulonglong2 W4s[39*32];      // 19,968 B
    __shared__ __align__(16) float ftile[2][39*TILE];    // 2 x 19,968 B

    // weights once per block
    {
        const ulonglong2* src = reinterpret_cast<const ulonglong2*>(g_W4);
        #pragma unroll
        for (int k = 0; k < 5; k++) {
            int idx = t + k*256;
            if (idx < 39*32) W4s[idx] = src[idx];
        }
    }

    const int tile0 = blockIdx.x * NT;

    auto issue_tile = [&](int tile, int buf) {
        const int e0 = tile * TILE;
        #pragma unroll
        for (int k = 0; k < 5; k++) {
            int idx = t + k*256;
            if (idx < NCHUNK) {
                int f = idx >> 5, e4 = idx & 31;       // 32 chunks per f-row
                cp16(&ftile[buf][f*TILE + e4*4],
                     &g_feat[(size_t)f * NEDGE + e0 + e4*4]);
            }
        }
    };

    // prefetch tile 0
    issue_tile(tile0, 0);
    CP_COMMIT();

    const float4 b4 = reinterpret_cast<const float4*>(be)[l];
    const float4 g4 = reinterpret_cast<const float4*>(ge)[l];
    const float4 t4 = reinterpret_cast<const float4*>(betae)[l];

    #pragma unroll 1
    for (int it = 0; it < NT; it++) {
        if (it + 1 < NT) {
            issue_tile(tile0 + it + 1, (it + 1) & 1);
            CP_COMMIT();
            CP_WAIT(1);
        } else {
            CP_WAIT(0);
        }
        __syncthreads();

        const float* buf = ftile[it & 1];
        const int e0 = (tile0 + it) * TILE;

        // acc[p][c]: edge pair (h*16+2p, h*16+2p+1), channel 4l+c
        unsigned long long acc[8][4];
        {
            unsigned long long b0 = pack2(b4.x, b4.x);
            unsigned long long b1 = pack2(b4.y, b4.y);
            unsigned long long b2 = pack2(b4.z, b4.z);
            unsigned long long b3 = pack2(b4.w, b4.w);
            #pragma unroll
            for (int p = 0; p < 8; p++) {
                acc[p][0] = b0; acc[p][1] = b1; acc[p][2] = b2; acc[p][3] = b3;
            }
        }

        #pragma unroll
        for (int f = 0; f < 39; f++) {
            ulonglong2 wq = W4s[f*32 + l];               // (w0,w1),(w2,w3)
            float2 wx = unpack2(wq.x);
            float2 wy = unpack2(wq.y);
            unsigned long long wd0 = pack2(wx.x, wx.x);
            unsigned long long wd1 = pack2(wx.y, wx.y);
            unsigned long long wd2 = pack2(wy.x, wy.x);
            unsigned long long wd3 = pack2(wy.y, wy.y);
            const ulonglong2* fp = reinterpret_cast<const ulonglong2*>(
                buf + f*TILE + h*16);                    // broadcast LDS.128
            #pragma unroll
            for (int k = 0; k < 4; k++) {
                ulonglong2 v = fp[k];   // v.x=(f_e,f_e+1), v.y=(f_e+2,f_e+3)
                fma2(acc[2*k  ][0], wd0, v.x);
                fma2(acc[2*k  ][1], wd1, v.x);
                fma2(acc[2*k  ][2], wd2, v.x);
                fma2(acc[2*k  ][3], wd3, v.x);
                fma2(acc[2*k+1][0], wd0, v.y);
                fma2(acc[2*k+1][1], wd1, v.y);
                fma2(acc[2*k+1][2], wd2, v.y);
                fma2(acc[2*k+1][3], wd3, v.y);
            }
        }

        // epilogue: LN per edge; (s1,s2) packed as one f32x2 chain per parity
        #pragma unroll
        for (int p = 0; p < 8; p++) {
            float2 a0 = unpack2(acc[p][0]);
            float2 a1 = unpack2(acc[p][1]);
            float2 a2 = unpack2(acc[p][2]);
            float2 a3 = unpack2(acc[p][3]);
            float s1e = (a0.x + a1.x) + (a2.x + a3.x);
            float s1o = (a0.y + a1.y) + (a2.y + a3.y);
            float s2e = a0.x*a0.x + a1.x*a1.x + a2.x*a2.x + a3.x*a3.x;
            float s2o = a0.y*a0.y + a1.y*a1.y + a2.y*a2.y + a3.y*a3.y;
            unsigned long long se = pack2(s1e, s2e);
            unsigned long long so = pack2(s1o, s2o);
            #pragma unroll
            for (int o = 16; o > 0; o >>= 1) {
                se = add2(se, __shfl_xor_sync(0xffffffffu, se, o));
                so = add2(so, __shfl_xor_sync(0xffffffffu, so, o));
            }
            float2 re = unpack2(se);   // (s1e, s2e)
            float2 ro = unpack2(so);   // (s1o, s2o)
            float mue  = re.x * (1.f/128.f);
            float muo  = ro.x * (1.f/128.f);
            float ire  = 1.f / sqrtf(re.y * (1.f/128.f) - mue*mue + 1e-5f);
            float iro  = 1.f / sqrtf(ro.y * (1.f/128.f) - muo*muo + 1e-5f);

            int ee = e0 + h*16 + 2*p;
            float4 oe, oo;
            oe.x = (a0.x - mue) * ire * g4.x + t4.x;
            oe.y = (a1.x - mue) * ire * g4.y + t4.y;
            oe.z = (a2.x - mue) * ire * g4.z + t4.z;
            oe.w = (a3.x - mue) * ire * g4.w + t4.w;
            oo.x = (a0.y - muo) * iro * g4.x + t4.x;
            oo.y = (a1.y - muo) * iro * g4.y + t4.y;
            oo.z = (a2.y - muo) * iro * g4.z + t4.z;
            oo.w = (a3.y - muo) * iro * g4.w + t4.w;
            reinterpret_cast<float4*>(out + E_OFF + (size_t)ee * CH)[l]       = oe;
            reinterpret_cast<float4*>(out + E_OFF + (size_t)(ee + 1) * CH)[l] = oo;
        }
        __syncthreads();   // buffer free before it+2 overwrite
    }
}

// ======================================================================
extern "C" void kernel_launch(void* const* d_in, const int* in_sizes, int n_in,
                              void* d_out, int out_size)
{
    const float* X      = (const float*)d_in[0];
    // d_in[1] = mask (all ones; unused)
    const float* W_node = (const float*)d_in[2];
    const float* b_node = (const float*)d_in[3];
    const float* g_node = (const float*)d_in[4];
    const float* be_node= (const float*)d_in[5];
    const float* W_edge = (const float*)d_in[6];
    const float* b_edge = (const float*)d_in[7];
    const float* g_edge = (const float*)d_in[8];
    const float* be_edge= (const float*)d_in[9];
    float* out = (float*)d_out;

    knn_kernel<<<dim3(LL/16, NB), 512>>>(X, out);
    node_kernel<<<NB*LL/8, 256>>>(X, W_node, b_node, g_node, be_node, out);
    efeat_kernel<<<(NEDGE + 255)/256, 256>>>(X, W_edge);
    egemm_kernel<<<NEDGE/(TILE*NT), 256>>>(b_edge, g_edge, be_edge, out);
}